// round 5
// baseline (speedup 1.0000x reference)
#include <cuda_runtime.h>
#include <cstdint>

// Segment-sum: out[src[e], :16] += edge_w[e, :16]  (f32).
// One cp.reduce.async.bulk.add.f32 (64B) per EDGE -> 3.2M bulk-engine ops
// instead of 12.8M RED.128 LSU ops (which hit the 4-cyc/SMSP atomic issue
// floor = the measured ~50us plateau of R1-R4).

static constexpr int F       = 16;
static constexpr int TILE_E  = 1024;                 // edges per CTA
static constexpr int THREADS = 256;                  // 4 edges per thread
static constexpr int ROW_B   = F * 4;                // 64 bytes per row
static constexpr size_t SMEM_BYTES = (size_t)TILE_E * ROW_B + TILE_E * 4;

__global__ void zero_out_kernel(float4* __restrict__ out, int n_vec) {
    int i = blockIdx.x * blockDim.x + threadIdx.x;
    if (i < n_vec) out[i] = make_float4(0.f, 0.f, 0.f, 0.f);
}

__device__ __forceinline__ uint32_t smem_u32(const void* p) {
    return (uint32_t)__cvta_generic_to_shared(p);
}

__global__ void __launch_bounds__(THREADS) scatter_bulkred_kernel(
        const int* __restrict__ src,
        const float4* __restrict__ w4,     // edge_w as float4[E*4]
        float* __restrict__ out,
        int E) {
    extern __shared__ char smem[];
    float4* s_w  = (float4*)smem;                       // [TILE_E*4] = 64KB
    int*    s_id = (int*)(smem + (size_t)TILE_E * ROW_B); // [TILE_E]

    const int e0 = blockIdx.x * TILE_E;                 // first edge of tile
    const int n  = min(TILE_E, E - e0);                 // edges in this tile
    if (n <= 0) return;
    const int tid = threadIdx.x;

    // ---- stage tile into SMEM (coalesced, streaming) ----
    const int nq = n * 4;                               // float4 count
    #pragma unroll 4
    for (int i = tid; i < nq; i += THREADS)
        s_w[i] = __ldcs(&w4[(size_t)e0 * 4 + i]);
    for (int i = tid; i < n; i += THREADS)
        s_id[i] = __ldg(&src[e0 + i]);

    // order generic SMEM writes before async-proxy (bulk engine) reads
    asm volatile("fence.proxy.async.shared::cta;" ::: "memory");
    __syncthreads();

    // ---- one 64B bulk reduce per edge ----
    #pragma unroll
    for (int j = 0; j < TILE_E / THREADS; j++) {
        const int el = tid + j * THREADS;               // coalesced edge pick
        if (el < n) {
            const int s = s_id[el];
            const float* gdst = out + (size_t)s * F;    // 64B-aligned row
            const uint32_t ssrc = smem_u32(&s_w[el * 4]);
            asm volatile(
                "cp.reduce.async.bulk.global.shared::cta.bulk_group.add.f32 "
                "[%0], [%1], %2;"
                :: "l"(gdst), "r"(ssrc), "r"(ROW_B)
                : "memory");
        }
    }
    asm volatile("cp.async.bulk.commit_group;" ::: "memory");
    // SMEM is recycled by the next CTA on this SM -> must drain before exit.
    asm volatile("cp.async.bulk.wait_group 0;" ::: "memory");
}

extern "C" void kernel_launch(void* const* d_in, const int* in_sizes, int n_in,
                              void* d_out, int out_size) {
    const int* edge  = (const int*)d_in[0];        // [2, E]; row 0 = src
    const float4* w4 = (const float4*)d_in[1];     // [E, 16] f32
    float* out       = (float*)d_out;              // [N, 16] f32

    const int E = in_sizes[1] / F;                 // 3,200,000
    const int n_out_vec = out_size / 4;

    // 1) zero the poisoned output (kernel path beat memset: 3.2 vs 4.4 us)
    {
        int threads = 256;
        int blocks = (n_out_vec + threads - 1) / threads;
        zero_out_kernel<<<blocks, threads>>>((float4*)d_out, n_out_vec);
    }
    // 2) bulk-reduce scatter, one CTA per 1024-edge tile
    {
        static bool attr_set = false;
        if (!attr_set) {
            cudaFuncSetAttribute(scatter_bulkred_kernel,
                                 cudaFuncAttributeMaxDynamicSharedMemorySize,
                                 (int)SMEM_BYTES);
            attr_set = true;
        }
        int blocks = (E + TILE_E - 1) / TILE_E;    // 3125
        scatter_bulkred_kernel<<<blocks, THREADS, SMEM_BYTES>>>(edge, w4, out, E);
    }
}

// round 7
// speedup vs baseline: 1.2971x; 1.2971x over previous
#include <cuda_runtime.h>
#include <cstdint>

// Segment-sum: out[src[e], :16] += edge_w[e, :16] (f32), E=3.2M, N=100k.
// HYBRID: two scatter engines run concurrently in one grid.
//  - RED blocks  (2/3 of bids): R2-style red.global.add.v4.f32 via LSU/L1tex.
//  - BULK blocks (1/3 of bids): TMA 1D bulk load of a 512-edge tile into smem
//    (no register staging), then one 64B cp.reduce.async.bulk per edge via
//    the TMA/bulk engine.
// The two paths bind on different SM-side issue resources; interleaved bids
// keep both engines fed throughout the launch.

static constexpr int F       = 16;
static constexpr int THREADS = 256;
static constexpr int TILE_E  = 512;                 // edges per bulk tile
static constexpr int ROW_B   = F * 4;               // 64 bytes
static constexpr int TILE_B  = TILE_E * ROW_B;      // 32768 bytes
static constexpr size_t SMEM_BYTES = TILE_B;        // dynamic smem

__global__ void zero_out_kernel(float4* __restrict__ out, int n_vec) {
    int i = blockIdx.x * blockDim.x + threadIdx.x;
    if (i < n_vec) out[i] = make_float4(0.f, 0.f, 0.f, 0.f);
}

__device__ __forceinline__ void red_v4(float* dst, float4 w) {
    asm volatile("red.global.add.v4.f32 [%0], {%1, %2, %3, %4};"
                 :: "l"(dst), "f"(w.x), "f"(w.y), "f"(w.z), "f"(w.w)
                 : "memory");
}

__device__ __forceinline__ uint32_t smem_u32(const void* p) {
    return (uint32_t)__cvta_generic_to_shared(p);
}

__global__ void __launch_bounds__(THREADS) hybrid_scatter_kernel(
        const int* __restrict__ src,
        const float4* __restrict__ w4,
        float* __restrict__ out,
        int RED_E,           // edges handled by RED path   (= first RED_E)
        int nBulk,           // number of bulk tiles
        int nRed) {          // number of RED sub-blocks
    extern __shared__ __align__(128) char smem[];
    __shared__ uint64_t mbar;

    const int bid = blockIdx.x;
    const int tid = threadIdx.x;

    // ---- bid -> (type, sub) interleaving: bulk on bid%3==0 ----
    bool is_bulk;
    int  sub;
    if (bid < 3 * nBulk) {
        if (bid % 3 == 0) { is_bulk = true;  sub = bid / 3; }
        else              { is_bulk = false; sub = bid - bid / 3 - 1; }
    } else {
        is_bulk = false; sub = 2 * nBulk + (bid - 3 * nBulk);
    }

    if (is_bulk) {
        if (sub >= nBulk) return;
        const int e0 = RED_E + sub * TILE_E;        // first edge of tile
        float4* s_w = (float4*)smem;                // [TILE_E*4]

        // issue src index loads early (overlap with TMA)
        const int s0 = __ldg(&src[e0 + tid]);
        const int s1 = __ldg(&src[e0 + THREADS + tid]);

        if (tid == 0) {
            uint32_t mb = smem_u32(&mbar);
            asm volatile("mbarrier.init.shared.b64 [%0], 1;" :: "r"(mb) : "memory");
        }
        __syncthreads();
        if (tid == 0) {
            uint32_t mb = smem_u32(&mbar);
            asm volatile("mbarrier.arrive.expect_tx.shared.b64 _, [%0], %1;"
                         :: "r"(mb), "r"(TILE_B) : "memory");
            asm volatile(
                "cp.async.bulk.shared::cta.global.mbarrier::complete_tx::bytes "
                "[%0], [%1], %2, [%3];"
                :: "r"(smem_u32(s_w)), "l"(&w4[(size_t)e0 * 4]),
                   "r"(TILE_B), "r"(mb)
                : "memory");
        }
        // wait phase 0
        {
            uint32_t mb = smem_u32(&mbar);
            uint32_t done;
            asm volatile(
                "{\n\t.reg .pred p;\n\t"
                "mbarrier.try_wait.parity.acquire.cta.shared::cta.b64 p, [%1], 0;\n\t"
                "selp.b32 %0, 1, 0, p;\n\t}"
                : "=r"(done) : "r"(mb) : "memory");
            while (!done) {
                asm volatile(
                    "{\n\t.reg .pred p;\n\t"
                    "mbarrier.try_wait.parity.acquire.cta.shared::cta.b64 p, [%1], 0, 0x989680;\n\t"
                    "selp.b32 %0, 1, 0, p;\n\t}"
                    : "=r"(done) : "r"(mb) : "memory");
            }
        }
        asm volatile("fence.proxy.async.shared::cta;" ::: "memory");

        // one 64B bulk reduce per edge (2 per thread)
        const uint32_t sb = smem_u32(s_w);
        asm volatile(
            "cp.reduce.async.bulk.global.shared::cta.bulk_group.add.f32 "
            "[%0], [%1], %2;"
            :: "l"(out + (size_t)s0 * F), "r"(sb + tid * ROW_B), "r"(ROW_B)
            : "memory");
        asm volatile(
            "cp.reduce.async.bulk.global.shared::cta.bulk_group.add.f32 "
            "[%0], [%1], %2;"
            :: "l"(out + (size_t)s1 * F), "r"(sb + (THREADS + tid) * ROW_B),
               "r"(ROW_B)
            : "memory");
        asm volatile("cp.async.bulk.commit_group;" ::: "memory");
        asm volatile("cp.async.bulk.wait_group 0;" ::: "memory");
    } else {
        if (sub >= nRed) return;
        // R2-style RED path over quad-items [0, RED_E*4)
        const int total = RED_E * 4;
        const int G = nRed * THREADS;
        const int t = sub * THREADS + tid;
        const int i0 = t, i1 = t + G, i2 = t + 2 * G, i3 = t + 3 * G;

        int s0 = 0, s1 = 0, s2 = 0, s3 = 0;
        if (i0 < total) s0 = __ldg(&src[i0 >> 2]);
        if (i1 < total) s1 = __ldg(&src[i1 >> 2]);
        if (i2 < total) s2 = __ldg(&src[i2 >> 2]);
        if (i3 < total) s3 = __ldg(&src[i3 >> 2]);

        float4 w0, w1, w2, w3;
        if (i0 < total) w0 = __ldcs(&w4[i0]);
        if (i1 < total) w1 = __ldcs(&w4[i1]);
        if (i2 < total) w2 = __ldcs(&w4[i2]);
        if (i3 < total) w3 = __ldcs(&w4[i3]);

        if (i0 < total) red_v4(out + (size_t)s0 * F + (i0 & 3) * 4, w0);
        if (i1 < total) red_v4(out + (size_t)s1 * F + (i1 & 3) * 4, w1);
        if (i2 < total) red_v4(out + (size_t)s2 * F + (i2 & 3) * 4, w2);
        if (i3 < total) red_v4(out + (size_t)s3 * F + (i3 & 3) * 4, w3);
    }
}

extern "C" void kernel_launch(void* const* d_in, const int* in_sizes, int n_in,
                              void* d_out, int out_size) {
    const int* edge  = (const int*)d_in[0];        // [2, E]; row 0 = src
    const float4* w4 = (const float4*)d_in[1];     // [E, 16] f32
    float* out       = (float*)d_out;              // [N, 16] f32

    const int E = in_sizes[1] / F;                 // 3,200,000
    const int n_out_vec = out_size / 4;

    // split: bulk path takes the back half in 512-edge tiles
    const int nBulk = (E / 2) / TILE_E;            // 3125
    const int RED_E = E - nBulk * TILE_E;          // 1,600,000
    const int redItems = RED_E * 4;
    const int nRed = (redItems + THREADS * 4 - 1) / (THREADS * 4);  // 6250

    int grid = 3 * nBulk;
    if (nRed > 2 * nBulk) grid += nRed - 2 * nBulk;

    // 1) zero the poisoned output
    {
        int threads = 256;
        int blocks = (n_out_vec + threads - 1) / threads;
        zero_out_kernel<<<blocks, threads>>>((float4*)d_out, n_out_vec);
    }
    // 2) hybrid scatter
    hybrid_scatter_kernel<<<grid, THREADS, SMEM_BYTES>>>(
        edge, w4, out, RED_E, nBulk, nRed);
}

// round 9
// speedup vs baseline: 1.3233x; 1.0202x over previous
#include <cuda_runtime.h>
#include <cstdint>

// Segment-sum: out[src[e], f] += edge_w[e, f], F=16 (f32), E=3.2M, N=100k.
// Scatter is pinned at the L2 atomic-RMW wall (~50us; proven invariant across
// LSU-RED, TMA bulk-reduce, and hybrid forms). Remaining win: hide the
// output-zeroing kernel under the scatter's load phase via PDL
// (programmatic dependent launch): scatter launches early, issues all its
// global loads (which never touch `out`), then griddepcontrol.wait's for the
// zero kernel before issuing reductions.

static constexpr int F = 16;

__global__ void zero_out_kernel(float4* __restrict__ out, int n_vec) {
    int i = blockIdx.x * blockDim.x + threadIdx.x;
    if (i < n_vec) out[i] = make_float4(0.f, 0.f, 0.f, 0.f);
    // Signal dependent grid: prior stores by this thread are visible to
    // dependents after their griddepcontrol.wait.
    asm volatile("griddepcontrol.launch_dependents;" ::: "memory");
}

__device__ __forceinline__ void red_v4(float* dst, float4 w) {
    asm volatile("red.global.add.v4.f32 [%0], {%1, %2, %3, %4};"
                 :: "l"(dst), "f"(w.x), "f"(w.y), "f"(w.z), "f"(w.w)
                 : "memory");
}

__global__ void __launch_bounds__(256) scatter_add_kernel(
        const int* __restrict__ src,
        const float4* __restrict__ w4,
        float* __restrict__ out,
        int total) {                      // total = E*4 quad-items
    const int G = blockDim.x * gridDim.x;
    const int t = blockIdx.x * blockDim.x + threadIdx.x;

    const int i0 = t;
    const int i1 = t + G;
    const int i2 = t + 2 * G;
    const int i3 = t + 3 * G;

    // ---- all loads first (overlap with the zero kernel via PDL) ----
    int s0 = 0, s1 = 0, s2 = 0, s3 = 0;
    if (i0 < total) s0 = __ldg(&src[i0 >> 2]);
    if (i1 < total) s1 = __ldg(&src[i1 >> 2]);
    if (i2 < total) s2 = __ldg(&src[i2 >> 2]);
    if (i3 < total) s3 = __ldg(&src[i3 >> 2]);

    float4 w0, w1, w2, w3;
    if (i0 < total) w0 = __ldcs(&w4[i0]);
    if (i1 < total) w1 = __ldcs(&w4[i1]);
    if (i2 < total) w2 = __ldcs(&w4[i2]);
    if (i3 < total) w3 = __ldcs(&w4[i3]);

    // ---- wait for the zero kernel's stores to be visible ----
    asm volatile("griddepcontrol.wait;" ::: "memory");

    // ---- reductions (4 lanes cover one 64B row -> coalesced RED group) ----
    if (i0 < total) red_v4(out + (size_t)s0 * F + (i0 & 3) * 4, w0);
    if (i1 < total) red_v4(out + (size_t)s1 * F + (i1 & 3) * 4, w1);
    if (i2 < total) red_v4(out + (size_t)s2 * F + (i2 & 3) * 4, w2);
    if (i3 < total) red_v4(out + (size_t)s3 * F + (i3 & 3) * 4, w3);
}

extern "C" void kernel_launch(void* const* d_in, const int* in_sizes, int n_in,
                              void* d_out, int out_size) {
    const int* edge  = (const int*)d_in[0];        // [2, E]; row 0 = src
    const float4* w4 = (const float4*)d_in[1];     // [E, 16] f32 == [E*4] float4
    float* out       = (float*)d_out;              // [N, 16] f32

    const int E = in_sizes[1] / F;                 // 3,200,000
    const int n_out_vec = out_size / 4;            // N*16/4 float4s

    // 1) zero the poisoned output (primary grid)
    {
        int threads = 256;
        int blocks = (n_out_vec + threads - 1) / threads;
        zero_out_kernel<<<blocks, threads>>>((float4*)d_out, n_out_vec);
    }
    // 2) scatter-add, launched as a programmatic dependent of the zero kernel
    {
        int total = E * 4;                          // 12.8M quad-items
        int threads = 256;
        int blocks = (total + threads * 4 - 1) / (threads * 4);  // 12500

        cudaLaunchConfig_t cfg = {};
        cfg.gridDim  = dim3(blocks, 1, 1);
        cfg.blockDim = dim3(threads, 1, 1);
        cfg.dynamicSmemBytes = 0;
        cfg.stream = 0;                             // legacy default (captured)

        cudaLaunchAttribute attr[1];
        attr[0].id = cudaLaunchAttributeProgrammaticStreamSerialization;
        attr[0].val.programmaticStreamSerializationAllowed = 1;
        cfg.attrs = attr;
        cfg.numAttrs = 1;

        cudaLaunchKernelEx(&cfg, scatter_add_kernel, edge, w4, out, total);
    }
}